// round 12
// baseline (speedup 1.0000x reference)
#include <cuda_runtime.h>
#include <cuda_fp16.h>
#include <cstdint>
#include <math.h>

// Shapes fixed by the reference: B=32, N=4096, D=256, H=256
#define BB 32
#define NN 4096
#define DD 256
#define HH 256
#define MTOT (BB * NN)          // 131072 rows
#define TILE_M 64               // rows per CTA
#define NTILES (MTOT / TILE_M)  // 2048
#define NCHUNK 128
#define KC 64                   // B d-chunk
#define SAW 264                 // A smem row stride in fp16 elems (full-D row + pad)
#define SB 72                   // B smem row stride in fp16 elems
#define A_BYTES (TILE_M * SAW * 2)    // 33792
#define B_BYTES (HH * SB * 2)         // 36864
#define DYN_SMEM (A_BYTES + 2 * B_BYTES)  // 107520

// ---------------- device scratch (no allocation allowed) ----------------
__device__ float g_scores[MTOT];
__device__ float g_bmax[BB];
__device__ float g_bden[BB];
__device__ float g_part[BB][NCHUNK][DD];
__device__ __align__(16) __half g_Wqh[HH * DD];
__device__ __align__(16) __half g_Wkh[HH * DD];

// ---------------- helpers ----------------
static __device__ __forceinline__ uint32_t smem_u32(const void* p) {
    uint32_t a;
    asm("{ .reg .u64 t; cvta.to.shared.u64 t, %1; cvt.u32.u64 %0, t; }"
        : "=r"(a) : "l"(p));
    return a;
}

static __device__ __forceinline__ void ldsm_x4(uint32_t& r0, uint32_t& r1,
                                               uint32_t& r2, uint32_t& r3,
                                               uint32_t addr) {
    asm volatile("ldmatrix.sync.aligned.m8n8.x4.shared.b16 {%0,%1,%2,%3}, [%4];"
                 : "=r"(r0), "=r"(r1), "=r"(r2), "=r"(r3) : "r"(addr));
}

static __device__ __forceinline__ void mma_f16(float* c, const uint32_t* a,
                                               uint32_t b0, uint32_t b1) {
    asm volatile(
        "mma.sync.aligned.m16n8k16.row.col.f32.f16.f16.f32 "
        "{%0,%1,%2,%3}, {%4,%5,%6,%7}, {%8,%9}, {%0,%1,%2,%3};"
        : "+f"(c[0]), "+f"(c[1]), "+f"(c[2]), "+f"(c[3])
        : "r"(a[0]), "r"(a[1]), "r"(a[2]), "r"(a[3]), "r"(b0), "r"(b1));
}

static __device__ __forceinline__ void cp_async16(uint32_t saddr, const void* gptr) {
    asm volatile("cp.async.cg.shared.global [%0], [%1], 16;"
                 :: "r"(saddr), "l"(gptr) : "memory");
}
#define CP_COMMIT() asm volatile("cp.async.commit_group;" ::: "memory")
#define CP_WAIT0()  asm volatile("cp.async.wait_group 0;" ::: "memory")

static __device__ __forceinline__ uint32_t pack_h(__half a, __half b) {
    __half2 t(a, b);
    return *reinterpret_cast<uint32_t*>(&t);
}

// Accurate fp32 tanh (Eigen-style rational, ~few-ulp in [-7.9, 7.9]).
static __device__ __forceinline__ float tanh_fast(float x) {
    float xc = fminf(fmaxf(x, -7.90531110763549805f), 7.90531110763549805f);
    float x2 = xc * xc;
    float p = fmaf(x2, -2.76076847742355e-16f, 2.00018790482477e-13f);
    p = fmaf(p, x2, -8.60467152213735e-11f);
    p = fmaf(p, x2, 5.12229709037114e-08f);
    p = fmaf(p, x2, 1.48572235717979e-05f);
    p = fmaf(p, x2, 6.37261928875436e-04f);
    p = fmaf(p, x2, 4.89352455891786e-03f);
    float q = fmaf(x2, 1.19825839466702e-06f, 1.18534705686654e-04f);
    q = fmaf(q, x2, 2.26843463243900e-03f);
    q = fmaf(q, x2, 4.89352518554385e-03f);
    return __fdividef(xc * p, q);
}

// =====================================================================
// Setup: convert Wq/Wk fp32 -> fp16 in global scratch.
// =====================================================================
__global__ void wsplit_kernel(const float* __restrict__ Wq, const float* __restrict__ Wk) {
    const int i = blockIdx.x * 256 + threadIdx.x;
    g_Wqh[i] = __float2half_rn(Wq[i]);
    g_Wkh[i] = __float2half_rn(Wk[i]);
}

// =====================================================================
// Scores via HMMA, single fp16 pass. CTA tile: 64 rows x 256 h (full H).
// A: single smem buffer holding the FULL 64x256 fp16 tile for the current
//    source (Q then K), loaded once per source at it=0/it=4.
// B: double-buffered KC=64 chunks via cp.async.
// 8 iterations: it<4 -> Q x Wq chunk (it&3), it>=4 -> K x Wk chunk (it&3).
// =====================================================================
__global__ __launch_bounds__(256, 2)
void scores_mma_kernel(const float* __restrict__ Q, const float* __restrict__ K,
                       const float* __restrict__ Wv) {
    extern __shared__ __align__(128) char dyn[];
    __shared__ float s_wv[HH];
    __shared__ float s_red[4][TILE_M];

    const int tid = threadIdx.x;
    const int lane = tid & 31;
    const int wid = tid >> 5;
    const int warp_m = wid & 1;      // 2 m-groups of 32 rows
    const int warp_n = wid >> 1;     // 4 n-groups of 64 cols
    const int m0 = blockIdx.x * TILE_M;

    s_wv[tid] = Wv[tid];

    const uint32_t base = smem_u32(dyn);
    const uint32_t sA = base;                       // 64 x 264 fp16
#define SB_TILE(buf) (base + A_BYTES + (buf) * B_BYTES)

    // A ldmatrix: row part per mi; column part added per k-step.
    uint32_t arow[2];   // [mi]
#pragma unroll
    for (int mi = 0; mi < 2; mi++)
        arow[mi] = sA + (uint32_t)((warp_m * 32 + mi * 16 + (lane & 15)) * (SAW * 2)
                                   + ((lane >> 4) * 8) * 2);
    // B ldmatrix offsets within a B tile; local ks 0..3
    uint32_t boff[4][4];   // [ntp][ks]
#pragma unroll
    for (int ntp = 0; ntp < 4; ntp++)
#pragma unroll
        for (int ks = 0; ks < 4; ks++)
            boff[ntp][ks] = (uint32_t)((warp_n * 64 + ntp * 16 + (lane & 7) + ((lane >> 4) << 3)) * (SB * 2)
                                       + ks * 32 + ((lane >> 3) & 1) * 16);

    // A load geometry: 64 rows x 64 float4 = 4096; 16 per thread
    const int ar = tid >> 2;          // base row 0..63
    const int ac0 = tid & 3;          // float4 col base (j adds 4)
    // B cp.async geometry: 256 rows x 8 uint4 = 2048; 8 per thread
    // idx = tid + 256*j -> r = idx>>3, c8 = idx&7

    float c[2][8][4];
#pragma unroll
    for (int mi = 0; mi < 2; mi++)
#pragma unroll
        for (int nt = 0; nt < 8; nt++)
#pragma unroll
            for (int r = 0; r < 4; r++) c[mi][nt][r] = 0.f;

    // ---- prestage B(0) (Wq chunk 0) ----
#pragma unroll
    for (int j = 0; j < 8; j++) {
        const int idx = tid + 256 * j;
        const int r = idx >> 3, c8 = idx & 7;
        cp_async16(SB_TILE(0) + (uint32_t)(r * SB + c8 * 8) * 2,
                   g_Wqh + (size_t)r * DD + c8 * 8);
    }
    CP_COMMIT();

#pragma unroll 1
    for (int it = 0; it < 8; it++) {
        const int buf = it & 1;

        // ---- at source boundaries, (re)load full A tile ----
        if ((it & 3) == 0) {
            const float* X = (it < 4) ? Q : K;
            __syncthreads();   // protect sA against MMA(it-1) readers
#pragma unroll
            for (int j = 0; j < 16; j++) {
                const int c4 = ac0 + 4 * j;       // 0..63
                const float4 v = *reinterpret_cast<const float4*>(
                    X + (size_t)(m0 + ar) * DD + c4 * 4);
                const uint32_t h0 = pack_h(__float2half_rn(v.x), __float2half_rn(v.y));
                const uint32_t h1 = pack_h(__float2half_rn(v.z), __float2half_rn(v.w));
                asm volatile("st.shared.v2.u32 [%0], {%1, %2};"
                             :: "r"(sA + (uint32_t)(ar * SAW + c4 * 4) * 2),
                                "r"(h0), "r"(h1));
            }
        }

        CP_WAIT0();          // B(it) delivered
        __syncthreads();

        // ---- prefetch B(it+1) ----
        if (it < 7) {
            const int nit = it + 1;
            const int nd0 = (nit & 3) * KC;
            const __half* WhG = (nit < 4) ? g_Wqh : g_Wkh;
#pragma unroll
            for (int j = 0; j < 8; j++) {
                const int idx = tid + 256 * j;
                const int r = idx >> 3, c8 = idx & 7;
                cp_async16(SB_TILE(buf ^ 1) + (uint32_t)(r * SB + c8 * 8) * 2,
                           WhG + (size_t)r * DD + nd0 + c8 * 8);
            }
            CP_COMMIT();
        }

        // ---- MMA: 4 k-steps x 8 n-tiles; A col = (it&3)*64 + ks*16 ----
        const uint32_t acol = (uint32_t)((it & 3) * KC * 2);
#pragma unroll
        for (int ks = 0; ks < 4; ks++) {
            uint32_t a0[4], a1[4];
            ldsm_x4(a0[0], a0[1], a0[2], a0[3], arow[0] + acol + ks * 32);
            ldsm_x4(a1[0], a1[1], a1[2], a1[3], arow[1] + acol + ks * 32);
#pragma unroll
            for (int ntp = 0; ntp < 4; ntp++) {
                uint32_t b0, b1, b2, b3;
                ldsm_x4(b0, b1, b2, b3, SB_TILE(buf) + boff[ntp][ks]);
                mma_f16(c[0][ntp * 2 + 0], a0, b0, b1);
                mma_f16(c[0][ntp * 2 + 1], a0, b2, b3);
                mma_f16(c[1][ntp * 2 + 0], a1, b0, b1);
                mma_f16(c[1][ntp * 2 + 1], a1, b2, b3);
            }
        }
    }

    // ---- epilogue: tanh + Wv dot ----
    float sp[4] = {0.f, 0.f, 0.f, 0.f};
#pragma unroll
    for (int mi = 0; mi < 2; mi++)
#pragma unroll
        for (int nt = 0; nt < 8; nt++) {
            const int col = warp_n * 64 + nt * 8 + (lane & 3) * 2;
            const float w0 = s_wv[col], w1 = s_wv[col + 1];
            sp[mi * 2 + 0] = fmaf(w0, tanh_fast(c[mi][nt][0]),
                             fmaf(w1, tanh_fast(c[mi][nt][1]), sp[mi * 2 + 0]));
            sp[mi * 2 + 1] = fmaf(w0, tanh_fast(c[mi][nt][2]),
                             fmaf(w1, tanh_fast(c[mi][nt][3]), sp[mi * 2 + 1]));
        }

    // reduce 4 col-lanes -> row totals
#pragma unroll
    for (int i = 0; i < 4; i++) {
        sp[i] += __shfl_xor_sync(0xFFFFFFFFu, sp[i], 1);
        sp[i] += __shfl_xor_sync(0xFFFFFFFFu, sp[i], 2);
    }
    __syncthreads();
    if ((lane & 3) == 0) {
#pragma unroll
        for (int mi = 0; mi < 2; mi++)
#pragma unroll
            for (int half = 0; half < 2; half++) {
                const int row = warp_m * 32 + mi * 16 + half * 8 + (lane >> 2);
                s_red[warp_n][row] = sp[mi * 2 + half];
            }
    }
    __syncthreads();
    if (tid < TILE_M)
        g_scores[m0 + tid] = (s_red[0][tid] + s_red[1][tid])
                           + (s_red[2][tid] + s_red[3][tid]);
#undef SB_TILE
}

// =====================================================================
// Kernel B: per-batch max / first-occurrence argmax / softmax denominator.
// =====================================================================
__global__ __launch_bounds__(1024)
void stats_kernel(float* __restrict__ out, int out_size) {
    const int b = blockIdx.x;
    const int tid = threadIdx.x;
    const float* s = g_scores + (long)b * NN;

    float m = -INFINITY;
    int mi = 0;
    for (int n = tid; n < NN; n += 1024) {
        const float v = s[n];
        if (v > m) { m = v; mi = n; }
    }
    __shared__ float sm[1024];
    __shared__ int   si[1024];
    sm[tid] = m; si[tid] = mi;
    __syncthreads();
    for (int o = 512; o > 0; o >>= 1) {
        if (tid < o) {
            const float v = sm[tid + o]; const int vi = si[tid + o];
            if (v > sm[tid] || (v == sm[tid] && vi < si[tid])) { sm[tid] = v; si[tid] = vi; }
        }
        __syncthreads();
    }
    const float mx = sm[0];
    const int amax = si[0];
    __syncthreads();

    float acc = 0.f;
    for (int n = tid; n < NN; n += 1024) acc += expf(s[n] - mx);
    sm[tid] = acc;
    __syncthreads();
    for (int o = 512; o > 0; o >>= 1) {
        if (tid < o) sm[tid] += sm[tid + o];
        __syncthreads();
    }
    if (tid == 0) {
        g_bmax[b] = mx;
        g_bden[b] = sm[0];
        if (out_size >= BB * DD + BB) out[BB * DD + b] = (float)amax;
    }
}

// =====================================================================
// Kernel C: partial weighted sums (deterministic, no atomics)
// chunk = 32 rows; grid (NCHUNK=128, BB) = 4096 blocks.
// =====================================================================
#define CROWS (NN / NCHUNK)   // 32
__global__ void weighted_kernel(const float* __restrict__ V) {
    const int chunk = blockIdx.x;
    const int b = blockIdx.y;
    const int tid = threadIdx.x;

    __shared__ float w[CROWS];
    __shared__ float part[4][DD];
    const float mx = g_bmax[b];
    const float inv = 1.0f / g_bden[b];
    const int n0 = chunk * CROWS;
    if (tid < CROWS)
        w[tid] = expf(g_scores[(long)b * NN + n0 + tid] - mx) * inv;
    __syncthreads();

    const int rg = tid >> 6;        // row-group 0..3
    const int c4 = tid & 63;        // float4 column
    const float4* Vp = reinterpret_cast<const float4*>(
        V + ((long)b * NN + n0) * DD) + c4;
    float4 acc = {0.f, 0.f, 0.f, 0.f};
#pragma unroll
    for (int n = rg; n < CROWS; n += 4) {
        const float4 v = Vp[(long)n * (DD / 4)];
        const float ww = w[n];
        acc.x = fmaf(ww, v.x, acc.x);
        acc.y = fmaf(ww, v.y, acc.y);
        acc.z = fmaf(ww, v.z, acc.z);
        acc.w = fmaf(ww, v.w, acc.w);
    }
    *reinterpret_cast<float4*>(&part[rg][c4 * 4]) = acc;
    __syncthreads();
    g_part[b][chunk][tid] = part[0][tid] + part[1][tid] + part[2][tid] + part[3][tid];
}

// =====================================================================
// Kernel D: reduce partials -> out[b, d]
// =====================================================================
__global__ void finalize_kernel(float* __restrict__ out) {
    const int b = blockIdx.x;
    const int tid = threadIdx.x;
    float acc = 0.f;
#pragma unroll 8
    for (int c = 0; c < NCHUNK; c++) acc += g_part[b][c][tid];
    out[b * DD + tid] = acc;
}

// =====================================================================
extern "C" void kernel_launch(void* const* d_in, const int* in_sizes, int n_in,
                              void* d_out, int out_size) {
    const float* Q  = (const float*)d_in[0];
    const float* K  = (const float*)d_in[1];
    const float* V  = (const float*)d_in[2];
    const float* Wq = (const float*)d_in[3];
    const float* Wk = (const float*)d_in[4];
    const float* Wv = (const float*)d_in[5];
    float* out = (float*)d_out;

    cudaFuncSetAttribute(scores_mma_kernel,
                         cudaFuncAttributeMaxDynamicSharedMemorySize, DYN_SMEM);

    wsplit_kernel<<<HH * DD / 256, 256>>>(Wq, Wk);
    scores_mma_kernel<<<NTILES, 256, DYN_SMEM>>>(Q, K, Wv);
    stats_kernel<<<BB, 1024>>>(out, out_size);
    weighted_kernel<<<dim3(NCHUNK, BB), 256>>>(V);
    finalize_kernel<<<BB, DD>>>(out);
}

// round 14
// speedup vs baseline: 1.1076x; 1.1076x over previous
#include <cuda_runtime.h>
#include <cuda_fp16.h>
#include <cstdint>
#include <math.h>

// Shapes fixed by the reference: B=32, N=4096, D=256, H=256
#define BB 32
#define NN 4096
#define DD 256
#define HH 256
#define MTOT (BB * NN)          // 131072 rows
#define TILE_M 64               // rows per CTA
#define NTILES (MTOT / TILE_M)  // 2048
#define NCHUNK 128
#define KC 64                   // d-chunk
#define SA 72                   // padded smem row stride in fp16 elems (144 B)
#define A_BYTES (TILE_M * SA * 2)     // 9216
#define B_BYTES (HH * SA * 2)         // 36864
#define BUF_BYTES (A_BYTES + B_BYTES) // 46080
#define DYN_SMEM (2 * BUF_BYTES)      // 92160

// ---------------- device scratch (no allocation allowed) ----------------
__device__ float g_scores[MTOT];
__device__ float g_bmax[BB];
__device__ float g_bden[BB];
__device__ float g_part[BB][NCHUNK][DD];
__device__ int   g_cnt[BB];
__device__ __align__(16) __half g_Wqh[HH * DD];
__device__ __align__(16) __half g_Wkh[HH * DD];

// ---------------- helpers ----------------
static __device__ __forceinline__ uint32_t smem_u32(const void* p) {
    uint32_t a;
    asm("{ .reg .u64 t; cvta.to.shared.u64 t, %1; cvt.u32.u64 %0, t; }"
        : "=r"(a) : "l"(p));
    return a;
}

static __device__ __forceinline__ void ldsm_x4(uint32_t& r0, uint32_t& r1,
                                               uint32_t& r2, uint32_t& r3,
                                               uint32_t addr) {
    asm volatile("ldmatrix.sync.aligned.m8n8.x4.shared.b16 {%0,%1,%2,%3}, [%4];"
                 : "=r"(r0), "=r"(r1), "=r"(r2), "=r"(r3) : "r"(addr));
}

static __device__ __forceinline__ void mma_f16(float* c, const uint32_t* a,
                                               uint32_t b0, uint32_t b1) {
    asm volatile(
        "mma.sync.aligned.m16n8k16.row.col.f32.f16.f16.f32 "
        "{%0,%1,%2,%3}, {%4,%5,%6,%7}, {%8,%9}, {%0,%1,%2,%3};"
        : "+f"(c[0]), "+f"(c[1]), "+f"(c[2]), "+f"(c[3])
        : "r"(a[0]), "r"(a[1]), "r"(a[2]), "r"(a[3]), "r"(b0), "r"(b1));
}

static __device__ __forceinline__ void cp_async16(uint32_t saddr, const void* gptr) {
    asm volatile("cp.async.cg.shared.global [%0], [%1], 16;"
                 :: "r"(saddr), "l"(gptr) : "memory");
}
#define CP_COMMIT() asm volatile("cp.async.commit_group;" ::: "memory")
#define CP_WAIT0()  asm volatile("cp.async.wait_group 0;" ::: "memory")

static __device__ __forceinline__ uint32_t pack_h(__half a, __half b) {
    __half2 t(a, b);
    return *reinterpret_cast<uint32_t*>(&t);
}

// Accurate fp32 tanh (Eigen-style rational, ~few-ulp in [-7.9, 7.9]).
static __device__ __forceinline__ float tanh_fast(float x) {
    float xc = fminf(fmaxf(x, -7.90531110763549805f), 7.90531110763549805f);
    float x2 = xc * xc;
    float p = fmaf(x2, -2.76076847742355e-16f, 2.00018790482477e-13f);
    p = fmaf(p, x2, -8.60467152213735e-11f);
    p = fmaf(p, x2, 5.12229709037114e-08f);
    p = fmaf(p, x2, 1.48572235717979e-05f);
    p = fmaf(p, x2, 6.37261928875436e-04f);
    p = fmaf(p, x2, 4.89352455891786e-03f);
    float q = fmaf(x2, 1.19825839466702e-06f, 1.18534705686654e-04f);
    q = fmaf(q, x2, 2.26843463243900e-03f);
    q = fmaf(q, x2, 4.89352518554385e-03f);
    return __fdividef(xc * p, q);
}

// =====================================================================
// Setup: convert Wq/Wk fp32 -> fp16 in global scratch.
// =====================================================================
__global__ void wsplit_kernel(const float* __restrict__ Wq, const float* __restrict__ Wk) {
    const int i = blockIdx.x * 256 + threadIdx.x;
    g_Wqh[i] = __float2half_rn(Wq[i]);
    g_Wkh[i] = __float2half_rn(Wk[i]);
}

// =====================================================================
// Scores via HMMA, single fp16 pass (identical to the 192.1us R11 kernel).
// CTA tile: 64 rows x 256 h. KC=64 -> 8 pipeline iterations.
// =====================================================================
__global__ __launch_bounds__(256, 2)
void scores_mma_kernel(const float* __restrict__ Q, const float* __restrict__ K,
                       const float* __restrict__ Wv) {
    extern __shared__ __align__(128) char dyn[];
    __shared__ float s_wv[HH];
    __shared__ float s_red[4][TILE_M];

    const int tid = threadIdx.x;
    const int lane = tid & 31;
    const int wid = tid >> 5;
    const int warp_m = wid & 1;      // 2 m-groups of 32 rows
    const int warp_n = wid >> 1;     // 4 n-groups of 64 cols
    const int m0 = blockIdx.x * TILE_M;

    s_wv[tid] = Wv[tid];

    const uint32_t base = smem_u32(dyn);
#define SA_TILE(buf) (base + (buf) * BUF_BYTES)
#define SB_TILE(buf) (base + (buf) * BUF_BYTES + A_BYTES)

    uint32_t aoff[2][4];   // [mi][ks]
#pragma unroll
    for (int mi = 0; mi < 2; mi++)
#pragma unroll
        for (int ks = 0; ks < 4; ks++)
            aoff[mi][ks] = (uint32_t)((warp_m * 32 + mi * 16 + (lane & 15)) * (SA * 2)
                                      + (ks * 16 + ((lane >> 4) * 8)) * 2);
    uint32_t boff[4][4];   // [ntp][ks]
#pragma unroll
    for (int ntp = 0; ntp < 4; ntp++)
#pragma unroll
        for (int ks = 0; ks < 4; ks++)
            boff[ntp][ks] = (uint32_t)((warp_n * 64 + ntp * 16 + (lane & 7) + ((lane >> 4) << 3)) * (SA * 2)
                                       + ks * 32 + ((lane >> 3) & 1) * 16);

    float c[2][8][4];
#pragma unroll
    for (int mi = 0; mi < 2; mi++)
#pragma unroll
        for (int nt = 0; nt < 8; nt++)
#pragma unroll
            for (int r = 0; r < 4; r++) c[mi][nt][r] = 0.f;

    uint32_t ah[8];   // staged converted A (4 float4 -> 8 h2)

    // ---- prestage it=0 (src=Q, d0=0) ----
    {
#pragma unroll
        for (int j = 0; j < 4; j++) {
            const int idx = tid + 256 * j;
            const int r = idx >> 4, c4 = idx & 15;
            const float4 v = *reinterpret_cast<const float4*>(
                Q + (size_t)(m0 + r) * DD + 0 + c4 * 4);
            ah[2*j]   = pack_h(__float2half_rn(v.x), __float2half_rn(v.y));
            ah[2*j+1] = pack_h(__float2half_rn(v.z), __float2half_rn(v.w));
        }
#pragma unroll
        for (int j = 0; j < 8; j++) {
            const int idx = tid + 256 * j;
            const int r = idx >> 3, c8 = idx & 7;
            cp_async16(SB_TILE(0) + (uint32_t)(r * SA + c8 * 8) * 2,
                       g_Wqh + (size_t)r * DD + c8 * 8);
        }
        CP_COMMIT();
    }

#pragma unroll 1
    for (int it = 0; it < 8; it++) {
        const int buf = it & 1;

        // ---- STS staged A ----
#pragma unroll
        for (int j = 0; j < 4; j++) {
            const int idx = tid + 256 * j;
            const int r = idx >> 4, c4 = idx & 15;
            const uint32_t soff = (uint32_t)(r * SA + c4 * 4) * 2;
            asm volatile("st.shared.v2.u32 [%0], {%1, %2};"
                         :: "r"(SA_TILE(buf) + soff), "r"(ah[2*j]), "r"(ah[2*j+1]));
        }
        CP_WAIT0();          // B(it) delivered
        __syncthreads();

        // ---- prefetch (it+1): LDG+convert A to regs, cp.async B ----
        if (it < 7) {
            const int nit = it + 1;
            const int nsrc = nit >> 2;
            const int nd0 = (nit & 3) * KC;
            const float* X = nsrc ? K : Q;
            const __half* WhG = nsrc ? g_Wkh : g_Wqh;
#pragma unroll
            for (int j = 0; j < 8; j++) {
                const int idx = tid + 256 * j;
                const int r = idx >> 3, c8 = idx & 7;
                cp_async16(SB_TILE(buf ^ 1) + (uint32_t)(r * SA + c8 * 8) * 2,
                           WhG + (size_t)r * DD + nd0 + c8 * 8);
            }
            CP_COMMIT();
#pragma unroll
            for (int j = 0; j < 4; j++) {
                const int idx = tid + 256 * j;
                const int r = idx >> 4, c4 = idx & 15;
                const float4 v = *reinterpret_cast<const float4*>(
                    X + (size_t)(m0 + r) * DD + nd0 + c4 * 4);
                ah[2*j]   = pack_h(__float2half_rn(v.x), __float2half_rn(v.y));
                ah[2*j+1] = pack_h(__float2half_rn(v.z), __float2half_rn(v.w));
            }
        }

        // ---- MMA: 4 k-steps x 8 n-tiles ----
#pragma unroll
        for (int ks = 0; ks < 4; ks++) {
            uint32_t a0[4], a1[4];
            ldsm_x4(a0[0], a0[1], a0[2], a0[3], SA_TILE(buf) + aoff[0][ks]);
            ldsm_x4(a1[0], a1[1], a1[2], a1[3], SA_TILE(buf) + aoff[1][ks]);
#pragma unroll
            for (int ntp = 0; ntp < 4; ntp++) {
                uint32_t b0, b1, b2, b3;
                ldsm_x4(b0, b1, b2, b3, SB_TILE(buf) + boff[ntp][ks]);
                mma_f16(c[0][ntp * 2 + 0], a0, b0, b1);
                mma_f16(c[0][ntp * 2 + 1], a0, b2, b3);
                mma_f16(c[1][ntp * 2 + 0], a1, b0, b1);
                mma_f16(c[1][ntp * 2 + 1], a1, b2, b3);
            }
        }
    }

    // ---- epilogue: tanh + Wv dot ----
    float sp[4] = {0.f, 0.f, 0.f, 0.f};
#pragma unroll
    for (int mi = 0; mi < 2; mi++)
#pragma unroll
        for (int nt = 0; nt < 8; nt++) {
            const int col = warp_n * 64 + nt * 8 + (lane & 3) * 2;
            const float w0 = s_wv[col], w1 = s_wv[col + 1];
            sp[mi * 2 + 0] = fmaf(w0, tanh_fast(c[mi][nt][0]),
                             fmaf(w1, tanh_fast(c[mi][nt][1]), sp[mi * 2 + 0]));
            sp[mi * 2 + 1] = fmaf(w0, tanh_fast(c[mi][nt][2]),
                             fmaf(w1, tanh_fast(c[mi][nt][3]), sp[mi * 2 + 1]));
        }

#pragma unroll
    for (int i = 0; i < 4; i++) {
        sp[i] += __shfl_xor_sync(0xFFFFFFFFu, sp[i], 1);
        sp[i] += __shfl_xor_sync(0xFFFFFFFFu, sp[i], 2);
    }
    __syncthreads();
    if ((lane & 3) == 0) {
#pragma unroll
        for (int mi = 0; mi < 2; mi++)
#pragma unroll
            for (int half = 0; half < 2; half++) {
                const int row = warp_m * 32 + mi * 16 + half * 8 + (lane >> 2);
                s_red[warp_n][row] = sp[mi * 2 + half];
            }
    }
    __syncthreads();
    if (tid < TILE_M)
        g_scores[m0 + tid] = (s_red[0][tid] + s_red[1][tid])
                           + (s_red[2][tid] + s_red[3][tid]);
#undef SA_TILE
#undef SB_TILE
}

// =====================================================================
// Kernel B: per-batch max / argmax / denominator. Also resets the
// per-batch completion counter used by the fused weighted+finalize.
// =====================================================================
__global__ __launch_bounds__(1024)
void stats_kernel(float* __restrict__ out, int out_size) {
    const int b = blockIdx.x;
    const int tid = threadIdx.x;
    const float* s = g_scores + (long)b * NN;

    if (tid == 0) g_cnt[b] = 0;

    float m = -INFINITY;
    int mi = 0;
    for (int n = tid; n < NN; n += 1024) {
        const float v = s[n];
        if (v > m) { m = v; mi = n; }
    }
    __shared__ float sm[1024];
    __shared__ int   si[1024];
    sm[tid] = m; si[tid] = mi;
    __syncthreads();
    for (int o = 512; o > 0; o >>= 1) {
        if (tid < o) {
            const float v = sm[tid + o]; const int vi = si[tid + o];
            if (v > sm[tid] || (v == sm[tid] && vi < si[tid])) { sm[tid] = v; si[tid] = vi; }
        }
        __syncthreads();
    }
    const float mx = sm[0];
    const int amax = si[0];
    __syncthreads();

    float acc = 0.f;
    for (int n = tid; n < NN; n += 1024) acc += expf(s[n] - mx);
    sm[tid] = acc;
    __syncthreads();
    for (int o = 512; o > 0; o >>= 1) {
        if (tid < o) sm[tid] += sm[tid + o];
        __syncthreads();
    }
    if (tid == 0) {
        g_bmax[b] = mx;
        g_bden[b] = sm[0];
        if (out_size >= BB * DD + BB) out[BB * DD + b] = (float)amax;
    }
}

// =====================================================================
// Kernel C: partial weighted sums + fused deterministic finalize.
// Each block writes its partial, then the LAST block to finish batch b
// performs the fixed-order chunk sum (bitwise deterministic: same values,
// same order, independent of which block runs it; g_part is L2-hot).
// =====================================================================
#define CROWS (NN / NCHUNK)   // 32
__global__ void weighted_kernel(const float* __restrict__ V, float* __restrict__ out) {
    const int chunk = blockIdx.x;
    const int b = blockIdx.y;
    const int tid = threadIdx.x;

    __shared__ float w[CROWS];
    __shared__ float part[4][DD];
    __shared__ int s_last;
    const float mx = g_bmax[b];
    const float inv = 1.0f / g_bden[b];
    const int n0 = chunk * CROWS;
    if (tid < CROWS)
        w[tid] = expf(g_scores[(long)b * NN + n0 + tid] - mx) * inv;
    __syncthreads();

    const int rg = tid >> 6;        // row-group 0..3
    const int c4 = tid & 63;        // float4 column
    const float4* Vp = reinterpret_cast<const float4*>(
        V + ((long)b * NN + n0) * DD) + c4;
    float4 acc = {0.f, 0.f, 0.f, 0.f};
#pragma unroll
    for (int n = rg; n < CROWS; n += 4) {
        const float4 v = Vp[(long)n * (DD / 4)];
        const float ww = w[n];
        acc.x = fmaf(ww, v.x, acc.x);
        acc.y = fmaf(ww, v.y, acc.y);
        acc.z = fmaf(ww, v.z, acc.z);
        acc.w = fmaf(ww, v.w, acc.w);
    }
    *reinterpret_cast<float4*>(&part[rg][c4 * 4]) = acc;
    __syncthreads();
    g_part[b][chunk][tid] = part[0][tid] + part[1][tid] + part[2][tid] + part[3][tid];

    // ---- completion protocol ----
    __threadfence();                        // partial visible before count
    if (tid == 0)
        s_last = (atomicAdd(&g_cnt[b], 1) == NCHUNK - 1);
    __syncthreads();
    if (s_last) {
        // all NCHUNK partials for batch b are globally visible here
        float t = 0.f;
#pragma unroll 8
        for (int c = 0; c < NCHUNK; c++) t += g_part[b][c][tid];
        out[b * DD + tid] = t;
    }
}

// =====================================================================
extern "C" void kernel_launch(void* const* d_in, const int* in_sizes, int n_in,
                              void* d_out, int out_size) {
    const float* Q  = (const float*)d_in[0];
    const float* K  = (const float*)d_in[1];
    const float* V  = (const float*)d_in[2];
    const float* Wq = (const float*)d_in[3];
    const float* Wk = (const float*)d_in[4];
    const float* Wv = (const float*)d_in[5];
    float* out = (float*)d_out;

    cudaFuncSetAttribute(scores_mma_kernel,
                         cudaFuncAttributeMaxDynamicSharedMemorySize, DYN_SMEM);

    wsplit_kernel<<<HH * DD / 256, 256>>>(Wq, Wk);
    scores_mma_kernel<<<NTILES, 256, DYN_SMEM>>>(Q, K, Wv);
    stats_kernel<<<BB, 1024>>>(out, out_size);
    weighted_kernel<<<dim3(NCHUNK, BB), 256>>>(V, out);
}

// round 15
// speedup vs baseline: 1.2370x; 1.1169x over previous
#include <cuda_runtime.h>
#include <cuda_fp16.h>
#include <cstdint>
#include <math.h>

// Shapes fixed by the reference: B=32, N=4096, D=256, H=256
#define BB 32
#define NN 4096
#define DD 256
#define HH 256
#define MTOT (BB * NN)          // 131072 rows
#define TILE_M 64               // rows per CTA
#define NTILES (MTOT / TILE_M)  // 2048
#define NCHUNK 64
#define KC 64                   // d-chunk
#define SA 72                   // padded smem row stride in fp16 elems (144 B)
#define A_BYTES (TILE_M * SA * 2)     // 9216
#define B_BYTES (HH * SA * 2)         // 36864
#define BUF_BYTES (A_BYTES + B_BYTES) // 46080
#define DYN_SMEM (2 * BUF_BYTES)      // 92160

// ---------------- device scratch (no allocation allowed) ----------------
__device__ float g_scores[MTOT];
__device__ float g_bmax[BB];
__device__ float g_bden[BB];
__device__ float g_part[BB][NCHUNK][DD];
__device__ int   g_cnt[BB];
__device__ __align__(16) __half g_Wqh[HH * DD];
__device__ __align__(16) __half g_Wkh[HH * DD];

// ---------------- helpers ----------------
static __device__ __forceinline__ uint32_t smem_u32(const void* p) {
    uint32_t a;
    asm("{ .reg .u64 t; cvta.to.shared.u64 t, %1; cvt.u32.u64 %0, t; }"
        : "=r"(a) : "l"(p));
    return a;
}

static __device__ __forceinline__ void ldsm_x4(uint32_t& r0, uint32_t& r1,
                                               uint32_t& r2, uint32_t& r3,
                                               uint32_t addr) {
    asm volatile("ldmatrix.sync.aligned.m8n8.x4.shared.b16 {%0,%1,%2,%3}, [%4];"
                 : "=r"(r0), "=r"(r1), "=r"(r2), "=r"(r3) : "r"(addr));
}

static __device__ __forceinline__ void mma_f16(float* c, const uint32_t* a,
                                               uint32_t b0, uint32_t b1) {
    asm volatile(
        "mma.sync.aligned.m16n8k16.row.col.f32.f16.f16.f32 "
        "{%0,%1,%2,%3}, {%4,%5,%6,%7}, {%8,%9}, {%0,%1,%2,%3};"
        : "+f"(c[0]), "+f"(c[1]), "+f"(c[2]), "+f"(c[3])
        : "r"(a[0]), "r"(a[1]), "r"(a[2]), "r"(a[3]), "r"(b0), "r"(b1));
}

static __device__ __forceinline__ void cp_async16(uint32_t saddr, const void* gptr) {
    asm volatile("cp.async.cg.shared.global [%0], [%1], 16;"
                 :: "r"(saddr), "l"(gptr) : "memory");
}
#define CP_COMMIT() asm volatile("cp.async.commit_group;" ::: "memory")
#define CP_WAIT0()  asm volatile("cp.async.wait_group 0;" ::: "memory")

static __device__ __forceinline__ uint32_t pack_h(__half a, __half b) {
    __half2 t(a, b);
    return *reinterpret_cast<uint32_t*>(&t);
}

// Hardware tanh (sm_75+): single MUFU-class instruction, abs err ~6e-4.
// Error budget: adds ~3e-4 to the score via the Wv dot (|Wv|~0.05, 256
// random-signed terms), independent of the 2.57e-4 fp16 GEMM error ->
// combined ~4e-4, well under the 1e-3 gate.
static __device__ __forceinline__ float tanh_fast(float x) {
    float y;
    asm("tanh.approx.f32 %0, %1;" : "=f"(y) : "f"(x));
    return y;
}

// =====================================================================
// Setup: convert Wq/Wk fp32 -> fp16 in global scratch.
// =====================================================================
__global__ void wsplit_kernel(const float* __restrict__ Wq, const float* __restrict__ Wk) {
    const int i = blockIdx.x * 256 + threadIdx.x;
    g_Wqh[i] = __float2half_rn(Wq[i]);
    g_Wkh[i] = __float2half_rn(Wk[i]);
}

// =====================================================================
// Scores via HMMA, single fp16 pass (R11 mainloop geometry).
// CTA tile: 64 rows x 256 h. KC=64 -> 8 pipeline iterations.
// =====================================================================
__global__ __launch_bounds__(256, 2)
void scores_mma_kernel(const float* __restrict__ Q, const float* __restrict__ K,
                       const float* __restrict__ Wv) {
    extern __shared__ __align__(128) char dyn[];
    __shared__ float s_wv[HH];
    __shared__ float s_red[4][TILE_M];

    const int tid = threadIdx.x;
    const int lane = tid & 31;
    const int wid = tid >> 5;
    const int warp_m = wid & 1;      // 2 m-groups of 32 rows
    const int warp_n = wid >> 1;     // 4 n-groups of 64 cols
    const int m0 = blockIdx.x * TILE_M;

    s_wv[tid] = Wv[tid];

    const uint32_t base = smem_u32(dyn);
#define SA_TILE(buf) (base + (buf) * BUF_BYTES)
#define SB_TILE(buf) (base + (buf) * BUF_BYTES + A_BYTES)

    uint32_t aoff[2][4];   // [mi][ks]
#pragma unroll
    for (int mi = 0; mi < 2; mi++)
#pragma unroll
        for (int ks = 0; ks < 4; ks++)
            aoff[mi][ks] = (uint32_t)((warp_m * 32 + mi * 16 + (lane & 15)) * (SA * 2)
                                      + (ks * 16 + ((lane >> 4) * 8)) * 2);
    uint32_t boff[4][4];   // [ntp][ks]
#pragma unroll
    for (int ntp = 0; ntp < 4; ntp++)
#pragma unroll
        for (int ks = 0; ks < 4; ks++)
            boff[ntp][ks] = (uint32_t)((warp_n * 64 + ntp * 16 + (lane & 7) + ((lane >> 4) << 3)) * (SA * 2)
                                       + ks * 32 + ((lane >> 3) & 1) * 16);

    float c[2][8][4];
#pragma unroll
    for (int mi = 0; mi < 2; mi++)
#pragma unroll
        for (int nt = 0; nt < 8; nt++)
#pragma unroll
            for (int r = 0; r < 4; r++) c[mi][nt][r] = 0.f;

    uint32_t ah[8];   // staged converted A (4 float4 -> 8 h2)

    // ---- prestage it=0 (src=Q, d0=0) ----
    {
#pragma unroll
        for (int j = 0; j < 4; j++) {
            const int idx = tid + 256 * j;
            const int r = idx >> 4, c4 = idx & 15;
            const float4 v = *reinterpret_cast<const float4*>(
                Q + (size_t)(m0 + r) * DD + 0 + c4 * 4);
            ah[2*j]   = pack_h(__float2half_rn(v.x), __float2half_rn(v.y));
            ah[2*j+1] = pack_h(__float2half_rn(v.z), __float2half_rn(v.w));
        }
#pragma unroll
        for (int j = 0; j < 8; j++) {
            const int idx = tid + 256 * j;
            const int r = idx >> 3, c8 = idx & 7;
            cp_async16(SB_TILE(0) + (uint32_t)(r * SA + c8 * 8) * 2,
                       g_Wqh + (size_t)r * DD + c8 * 8);
        }
        CP_COMMIT();
    }

#pragma unroll 1
    for (int it = 0; it < 8; it++) {
        const int buf = it & 1;

        // ---- STS staged A ----
#pragma unroll
        for (int j = 0; j < 4; j++) {
            const int idx = tid + 256 * j;
            const int r = idx >> 4, c4 = idx & 15;
            const uint32_t soff = (uint32_t)(r * SA + c4 * 4) * 2;
            asm volatile("st.shared.v2.u32 [%0], {%1, %2};"
                         :: "r"(SA_TILE(buf) + soff), "r"(ah[2*j]), "r"(ah[2*j+1]));
        }
        CP_WAIT0();          // B(it) delivered
        __syncthreads();

        // ---- prefetch (it+1): LDG+convert A to regs, cp.async B ----
        if (it < 7) {
            const int nit = it + 1;
            const int nsrc = nit >> 2;
            const int nd0 = (nit & 3) * KC;
            const float* X = nsrc ? K : Q;
            const __half* WhG = nsrc ? g_Wkh : g_Wqh;
#pragma unroll
            for (int j = 0; j < 8; j++) {
                const int idx = tid + 256 * j;
                const int r = idx >> 3, c8 = idx & 7;
                cp_async16(SB_TILE(buf ^ 1) + (uint32_t)(r * SA + c8 * 8) * 2,
                           WhG + (size_t)r * DD + nd0 + c8 * 8);
            }
            CP_COMMIT();
#pragma unroll
            for (int j = 0; j < 4; j++) {
                const int idx = tid + 256 * j;
                const int r = idx >> 4, c4 = idx & 15;
                const float4 v = *reinterpret_cast<const float4*>(
                    X + (size_t)(m0 + r) * DD + nd0 + c4 * 4);
                ah[2*j]   = pack_h(__float2half_rn(v.x), __float2half_rn(v.y));
                ah[2*j+1] = pack_h(__float2half_rn(v.z), __float2half_rn(v.w));
            }
        }

        // ---- MMA: 4 k-steps x 8 n-tiles ----
#pragma unroll
        for (int ks = 0; ks < 4; ks++) {
            uint32_t a0[4], a1[4];
            ldsm_x4(a0[0], a0[1], a0[2], a0[3], SA_TILE(buf) + aoff[0][ks]);
            ldsm_x4(a1[0], a1[1], a1[2], a1[3], SA_TILE(buf) + aoff[1][ks]);
#pragma unroll
            for (int ntp = 0; ntp < 4; ntp++) {
                uint32_t b0, b1, b2, b3;
                ldsm_x4(b0, b1, b2, b3, SB_TILE(buf) + boff[ntp][ks]);
                mma_f16(c[0][ntp * 2 + 0], a0, b0, b1);
                mma_f16(c[0][ntp * 2 + 1], a0, b2, b3);
                mma_f16(c[1][ntp * 2 + 0], a1, b0, b1);
                mma_f16(c[1][ntp * 2 + 1], a1, b2, b3);
            }
        }
    }

    // ---- epilogue: hw tanh + Wv dot ----
    float sp[4] = {0.f, 0.f, 0.f, 0.f};
#pragma unroll
    for (int mi = 0; mi < 2; mi++)
#pragma unroll
        for (int nt = 0; nt < 8; nt++) {
            const int col = warp_n * 64 + nt * 8 + (lane & 3) * 2;
            const float w0 = s_wv[col], w1 = s_wv[col + 1];
            sp[mi * 2 + 0] = fmaf(w0, tanh_fast(c[mi][nt][0]),
                             fmaf(w1, tanh_fast(c[mi][nt][1]), sp[mi * 2 + 0]));
            sp[mi * 2 + 1] = fmaf(w0, tanh_fast(c[mi][nt][2]),
                             fmaf(w1, tanh_fast(c[mi][nt][3]), sp[mi * 2 + 1]));
        }

#pragma unroll
    for (int i = 0; i < 4; i++) {
        sp[i] += __shfl_xor_sync(0xFFFFFFFFu, sp[i], 1);
        sp[i] += __shfl_xor_sync(0xFFFFFFFFu, sp[i], 2);
    }
    __syncthreads();
    if ((lane & 3) == 0) {
#pragma unroll
        for (int mi = 0; mi < 2; mi++)
#pragma unroll
            for (int half = 0; half < 2; half++) {
                const int row = warp_m * 32 + mi * 16 + half * 8 + (lane >> 2);
                s_red[warp_n][row] = sp[mi * 2 + half];
            }
    }
    __syncthreads();
    if (tid < TILE_M)
        g_scores[m0 + tid] = (s_red[0][tid] + s_red[1][tid])
                           + (s_red[2][tid] + s_red[3][tid]);
#undef SA_TILE
#undef SB_TILE
}

// =====================================================================
// Kernel B: per-batch max / argmax / denominator. Also resets the
// per-batch completion counter used by the fused weighted+finalize.
// =====================================================================
__global__ __launch_bounds__(1024)
void stats_kernel(float* __restrict__ out, int out_size) {
    const int b = blockIdx.x;
    const int tid = threadIdx.x;
    const float* s = g_scores + (long)b * NN;

    if (tid == 0) g_cnt[b] = 0;

    float m = -INFINITY;
    int mi = 0;
    for (int n = tid; n < NN; n += 1024) {
        const float v = s[n];
        if (v > m) { m = v; mi = n; }
    }
    __shared__ float sm[1024];
    __shared__ int   si[1024];
    sm[tid] = m; si[tid] = mi;
    __syncthreads();
    for (int o = 512; o > 0; o >>= 1) {
        if (tid < o) {
            const float v = sm[tid + o]; const int vi = si[tid + o];
            if (v > sm[tid] || (v == sm[tid] && vi < si[tid])) { sm[tid] = v; si[tid] = vi; }
        }
        __syncthreads();
    }
    const float mx = sm[0];
    const int amax = si[0];
    __syncthreads();

    float acc = 0.f;
    for (int n = tid; n < NN; n += 1024) acc += expf(s[n] - mx);
    sm[tid] = acc;
    __syncthreads();
    for (int o = 512; o > 0; o >>= 1) {
        if (tid < o) sm[tid] += sm[tid + o];
        __syncthreads();
    }
    if (tid == 0) {
        g_bmax[b] = mx;
        g_bden[b] = sm[0];
        if (out_size >= BB * DD + BB) out[BB * DD + b] = (float)amax;
    }
}

// =====================================================================
// Kernel C: partial weighted sums + fused deterministic finalize.
// chunk = 64 rows; grid (NCHUNK=64, BB) = 2048 blocks.
// Last block per batch does the fixed-order chunk sum (deterministic).
// =====================================================================
#define CROWS (NN / NCHUNK)   // 64
__global__ void weighted_kernel(const float* __restrict__ V, float* __restrict__ out) {
    const int chunk = blockIdx.x;
    const int b = blockIdx.y;
    const int tid = threadIdx.x;

    __shared__ float w[CROWS];
    __shared__ float part[4][DD];
    __shared__ int s_last;
    const float mx = g_bmax[b];
    const float inv = 1.0f / g_bden[b];
    const int n0 = chunk * CROWS;
    if (tid < CROWS)
        w[tid] = expf(g_scores[(long)b * NN + n0 + tid] - mx) * inv;
    __syncthreads();

    const int rg = tid >> 6;        // row-group 0..3
    const int c4 = tid & 63;        // float4 column
    const float4* Vp = reinterpret_cast<const float4*>(
        V + ((long)b * NN + n0) * DD) + c4;
    float4 acc = {0.f, 0.f, 0.f, 0.f};
#pragma unroll
    for (int n = rg; n < CROWS; n += 4) {
        const float4 v = Vp[(long)n * (DD / 4)];
        const float ww = w[n];
        acc.x = fmaf(ww, v.x, acc.x);
        acc.y = fmaf(ww, v.y, acc.y);
        acc.z = fmaf(ww, v.z, acc.z);
        acc.w = fmaf(ww, v.w, acc.w);
    }
    *reinterpret_cast<float4*>(&part[rg][c4 * 4]) = acc;
    __syncthreads();
    g_part[b][chunk][tid] = part[0][tid] + part[1][tid] + part[2][tid] + part[3][tid];

    // ---- completion protocol ----
    __threadfence();                        // partial visible before count
    if (tid == 0)
        s_last = (atomicAdd(&g_cnt[b], 1) == NCHUNK - 1);
    __syncthreads();
    if (s_last) {
        // all NCHUNK partials for batch b are globally visible here
        float t = 0.f;
#pragma unroll 8
        for (int c = 0; c < NCHUNK; c++) t += g_part[b][c][tid];
        out[b * DD + tid] = t;
    }
}

// =====================================================================
extern "C" void kernel_launch(void* const* d_in, const int* in_sizes, int n_in,
                              void* d_out, int out_size) {
    const float* Q  = (const float*)d_in[0];
    const float* K  = (const float*)d_in[1];
    const float* V  = (const float*)d_in[2];
    const float* Wq = (const float*)d_in[3];
    const float* Wk = (const float*)d_in[4];
    const float* Wv = (const float*)d_in[5];
    float* out = (float*)d_out;

    cudaFuncSetAttribute(scores_mma_kernel,
                         cudaFuncAttributeMaxDynamicSharedMemorySize, DYN_SMEM);

    wsplit_kernel<<<HH * DD / 256, 256>>>(Wq, Wk);
    scores_mma_kernel<<<NTILES, 256, DYN_SMEM>>>(Q, K, Wv);
    stats_kernel<<<BB, 1024>>>(out, out_size);
    weighted_kernel<<<dim3(NCHUNK, BB), 256>>>(V, out);
}

// round 16
// speedup vs baseline: 1.2611x; 1.0195x over previous
#include <cuda_runtime.h>
#include <cuda_fp16.h>
#include <cstdint>
#include <math.h>

// Shapes fixed by the reference: B=32, N=4096, D=256, H=256
#define BB 32
#define NN 4096
#define DD 256
#define HH 256
#define MTOT (BB * NN)          // 131072 rows
#define TILE_M 64               // rows per CTA
#define NTILES (MTOT / TILE_M)  // 2048
#define NCHUNK 64
#define KC 64                   // d-chunk
#define SA 72                   // padded smem row stride in fp16 elems (144 B)
#define A_BYTES (TILE_M * SA * 2)     // 9216
#define B_BYTES (HH * SA * 2)         // 36864
#define BUF_BYTES (A_BYTES + B_BYTES) // 46080
#define DYN_SMEM (2 * BUF_BYTES)      // 92160

// ---------------- device scratch (no allocation allowed) ----------------
__device__ float g_scores[MTOT];
__device__ float g_part[BB][NCHUNK][DD];
__device__ float g_denp[BB][NCHUNK];
__device__ unsigned long long g_keys[BB];   // packed (ordered score bits, NN-1-n)
__device__ int   g_cnt[BB];
__device__ __align__(16) __half g_Wqh[HH * DD];
__device__ __align__(16) __half g_Wkh[HH * DD];

// ---------------- helpers ----------------
static __device__ __forceinline__ uint32_t smem_u32(const void* p) {
    uint32_t a;
    asm("{ .reg .u64 t; cvta.to.shared.u64 t, %1; cvt.u32.u64 %0, t; }"
        : "=r"(a) : "l"(p));
    return a;
}

static __device__ __forceinline__ void ldsm_x4(uint32_t& r0, uint32_t& r1,
                                               uint32_t& r2, uint32_t& r3,
                                               uint32_t addr) {
    asm volatile("ldmatrix.sync.aligned.m8n8.x4.shared.b16 {%0,%1,%2,%3}, [%4];"
                 : "=r"(r0), "=r"(r1), "=r"(r2), "=r"(r3) : "r"(addr));
}

static __device__ __forceinline__ void mma_f16(float* c, const uint32_t* a,
                                               uint32_t b0, uint32_t b1) {
    asm volatile(
        "mma.sync.aligned.m16n8k16.row.col.f32.f16.f16.f32 "
        "{%0,%1,%2,%3}, {%4,%5,%6,%7}, {%8,%9}, {%0,%1,%2,%3};"
        : "+f"(c[0]), "+f"(c[1]), "+f"(c[2]), "+f"(c[3])
        : "r"(a[0]), "r"(a[1]), "r"(a[2]), "r"(a[3]), "r"(b0), "r"(b1));
}

static __device__ __forceinline__ void cp_async16(uint32_t saddr, const void* gptr) {
    asm volatile("cp.async.cg.shared.global [%0], [%1], 16;"
                 :: "r"(saddr), "l"(gptr) : "memory");
}
#define CP_COMMIT() asm volatile("cp.async.commit_group;" ::: "memory")
#define CP_WAIT0()  asm volatile("cp.async.wait_group 0;" ::: "memory")

static __device__ __forceinline__ uint32_t pack_h(__half a, __half b) {
    __half2 t(a, b);
    return *reinterpret_cast<uint32_t*>(&t);
}

// Hardware tanh (sm_75+): single MUFU-class instruction.
static __device__ __forceinline__ float tanh_fast(float x) {
    float y;
    asm("tanh.approx.f32 %0, %1;" : "=f"(y) : "f"(x));
    return y;
}

// Order-preserving float->uint map (monotonic for all finite floats).
static __device__ __forceinline__ uint32_t float_orderkey(float f) {
    uint32_t u = __float_as_uint(f);
    return (u & 0x80000000u) ? ~u : (u | 0x80000000u);
}
static __device__ __forceinline__ float orderkey_float(uint32_t u) {
    return __uint_as_float((u & 0x80000000u) ? (u & 0x7FFFFFFFu) : ~u);
}

// =====================================================================
// Setup: convert Wq/Wk fp32 -> fp16; block 0 resets per-batch scratch.
// =====================================================================
__global__ void wsplit_kernel(const float* __restrict__ Wq, const float* __restrict__ Wk) {
    const int i = blockIdx.x * 256 + threadIdx.x;
    g_Wqh[i] = __float2half_rn(Wq[i]);
    g_Wkh[i] = __float2half_rn(Wk[i]);
    if (blockIdx.x == 0 && threadIdx.x < BB) {
        g_cnt[threadIdx.x] = 0;
        g_keys[threadIdx.x] = 0ull;
    }
}

// =====================================================================
// Scores via HMMA, single fp16 pass (R11 mainloop). CTA: 64 rows x 256 h.
// Epilogue additionally publishes the per-batch (max, argmax) via a
// deterministic packed atomicMax (key = orderbits<<32 | (NN-1-n):
// max is order-independent; ties -> smallest n, matching first-occurrence).
// =====================================================================
__global__ __launch_bounds__(256, 2)
void scores_mma_kernel(const float* __restrict__ Q, const float* __restrict__ K,
                       const float* __restrict__ Wv) {
    extern __shared__ __align__(128) char dyn[];
    __shared__ float s_wv[HH];
    __shared__ float s_red[4][TILE_M];

    const int tid = threadIdx.x;
    const int lane = tid & 31;
    const int wid = tid >> 5;
    const int warp_m = wid & 1;      // 2 m-groups of 32 rows
    const int warp_n = wid >> 1;     // 4 n-groups of 64 cols
    const int m0 = blockIdx.x * TILE_M;

    s_wv[tid] = Wv[tid];

    const uint32_t base = smem_u32(dyn);
#define SA_TILE(buf) (base + (buf) * BUF_BYTES)
#define SB_TILE(buf) (base + (buf) * BUF_BYTES + A_BYTES)

    uint32_t aoff[2][4];   // [mi][ks]
#pragma unroll
    for (int mi = 0; mi < 2; mi++)
#pragma unroll
        for (int ks = 0; ks < 4; ks++)
            aoff[mi][ks] = (uint32_t)((warp_m * 32 + mi * 16 + (lane & 15)) * (SA * 2)
                                      + (ks * 16 + ((lane >> 4) * 8)) * 2);
    uint32_t boff[4][4];   // [ntp][ks]
#pragma unroll
    for (int ntp = 0; ntp < 4; ntp++)
#pragma unroll
        for (int ks = 0; ks < 4; ks++)
            boff[ntp][ks] = (uint32_t)((warp_n * 64 + ntp * 16 + (lane & 7) + ((lane >> 4) << 3)) * (SA * 2)
                                       + ks * 32 + ((lane >> 3) & 1) * 16);

    float c[2][8][4];
#pragma unroll
    for (int mi = 0; mi < 2; mi++)
#pragma unroll
        for (int nt = 0; nt < 8; nt++)
#pragma unroll
            for (int r = 0; r < 4; r++) c[mi][nt][r] = 0.f;

    uint32_t ah[8];   // staged converted A (4 float4 -> 8 h2)

    // ---- prestage it=0 (src=Q, d0=0) ----
    {
#pragma unroll
        for (int j = 0; j < 4; j++) {
            const int idx = tid + 256 * j;
            const int r = idx >> 4, c4 = idx & 15;
            const float4 v = *reinterpret_cast<const float4*>(
                Q + (size_t)(m0 + r) * DD + 0 + c4 * 4);
            ah[2*j]   = pack_h(__float2half_rn(v.x), __float2half_rn(v.y));
            ah[2*j+1] = pack_h(__float2half_rn(v.z), __float2half_rn(v.w));
        }
#pragma unroll
        for (int j = 0; j < 8; j++) {
            const int idx = tid + 256 * j;
            const int r = idx >> 3, c8 = idx & 7;
            cp_async16(SB_TILE(0) + (uint32_t)(r * SA + c8 * 8) * 2,
                       g_Wqh + (size_t)r * DD + c8 * 8);
        }
        CP_COMMIT();
    }

#pragma unroll 1
    for (int it = 0; it < 8; it++) {
        const int buf = it & 1;

        // ---- STS staged A ----
#pragma unroll
        for (int j = 0; j < 4; j++) {
            const int idx = tid + 256 * j;
            const int r = idx >> 4, c4 = idx & 15;
            const uint32_t soff = (uint32_t)(r * SA + c4 * 4) * 2;
            asm volatile("st.shared.v2.u32 [%0], {%1, %2};"
                         :: "r"(SA_TILE(buf) + soff), "r"(ah[2*j]), "r"(ah[2*j+1]));
        }
        CP_WAIT0();          // B(it) delivered
        __syncthreads();

        // ---- prefetch (it+1): LDG+convert A to regs, cp.async B ----
        if (it < 7) {
            const int nit = it + 1;
            const int nsrc = nit >> 2;
            const int nd0 = (nit & 3) * KC;
            const float* X = nsrc ? K : Q;
            const __half* WhG = nsrc ? g_Wkh : g_Wqh;
#pragma unroll
            for (int j = 0; j < 8; j++) {
                const int idx = tid + 256 * j;
                const int r = idx >> 3, c8 = idx & 7;
                cp_async16(SB_TILE(buf ^ 1) + (uint32_t)(r * SA + c8 * 8) * 2,
                           WhG + (size_t)r * DD + nd0 + c8 * 8);
            }
            CP_COMMIT();
#pragma unroll
            for (int j = 0; j < 4; j++) {
                const int idx = tid + 256 * j;
                const int r = idx >> 4, c4 = idx & 15;
                const float4 v = *reinterpret_cast<const float4*>(
                    X + (size_t)(m0 + r) * DD + nd0 + c4 * 4);
                ah[2*j]   = pack_h(__float2half_rn(v.x), __float2half_rn(v.y));
                ah[2*j+1] = pack_h(__float2half_rn(v.z), __float2half_rn(v.w));
            }
        }

        // ---- MMA: 4 k-steps x 8 n-tiles ----
#pragma unroll
        for (int ks = 0; ks < 4; ks++) {
            uint32_t a0[4], a1[4];
            ldsm_x4(a0[0], a0[1], a0[2], a0[3], SA_TILE(buf) + aoff[0][ks]);
            ldsm_x4(a1[0], a1[1], a1[2], a1[3], SA_TILE(buf) + aoff[1][ks]);
#pragma unroll
            for (int ntp = 0; ntp < 4; ntp++) {
                uint32_t b0, b1, b2, b3;
                ldsm_x4(b0, b1, b2, b3, SB_TILE(buf) + boff[ntp][ks]);
                mma_f16(c[0][ntp * 2 + 0], a0, b0, b1);
                mma_f16(c[0][ntp * 2 + 1], a0, b2, b3);
                mma_f16(c[1][ntp * 2 + 0], a1, b0, b1);
                mma_f16(c[1][ntp * 2 + 1], a1, b2, b3);
            }
        }
    }

    // ---- epilogue: hw tanh + Wv dot ----
    float sp[4] = {0.f, 0.f, 0.f, 0.f};
#pragma unroll
    for (int mi = 0; mi < 2; mi++)
#pragma unroll
        for (int nt = 0; nt < 8; nt++) {
            const int col = warp_n * 64 + nt * 8 + (lane & 3) * 2;
            const float w0 = s_wv[col], w1 = s_wv[col + 1];
            sp[mi * 2 + 0] = fmaf(w0, tanh_fast(c[mi][nt][0]),
                             fmaf(w1, tanh_fast(c[mi][nt][1]), sp[mi * 2 + 0]));
            sp[mi * 2 + 1] = fmaf(w0, tanh_fast(c[mi][nt][2]),
                             fmaf(w1, tanh_fast(c[mi][nt][3]), sp[mi * 2 + 1]));
        }

#pragma unroll
    for (int i = 0; i < 4; i++) {
        sp[i] += __shfl_xor_sync(0xFFFFFFFFu, sp[i], 1);
        sp[i] += __shfl_xor_sync(0xFFFFFFFFu, sp[i], 2);
    }
    __syncthreads();
    if ((lane & 3) == 0) {
#pragma unroll
        for (int mi = 0; mi < 2; mi++)
#pragma unroll
            for (int half = 0; half < 2; half++) {
                const int row = warp_m * 32 + mi * 16 + half * 8 + (lane >> 2);
                s_red[warp_n][row] = sp[mi * 2 + half];
            }
    }
    __syncthreads();
    if (tid < TILE_M) {
        const float sc = (s_red[0][tid] + s_red[1][tid])
                       + (s_red[2][tid] + s_red[3][tid]);
        g_scores[m0 + tid] = sc;
        // publish per-batch (max, argmax): key = orderbits<<32 | (NN-1-n)
        const int b = m0 >> 12;                 // 4096 rows per batch
        const int n = (m0 & (NN - 1)) + tid;
        unsigned long long key =
            ((unsigned long long)float_orderkey(sc) << 32) | (uint32_t)(NN - 1 - n);
#pragma unroll
        for (int o = 16; o > 0; o >>= 1) {
            unsigned long long other = __shfl_xor_sync(0xFFFFFFFFu, key, o);
            if (other > key) key = other;
        }
        if (lane == 0) atomicMax(&g_keys[b], key);   // 2 warps -> 2 atomics/CTA
    }
#undef SA_TILE
#undef SB_TILE
}

// =====================================================================
// Kernel C: weighted sums + denominator + fused deterministic finalize.
// chunk = 64 rows; grid (NCHUNK=64, BB). Blocks compute UNNORMALIZED
// partials exp(s-mx)*v and partial denominators; the last block per batch
// sums both in fixed chunk order and writes out = t/den and the argmax.
// =====================================================================
#define CROWS (NN / NCHUNK)   // 64
__global__ void weighted_kernel(const float* __restrict__ V, float* __restrict__ out,
                                int out_size) {
    const int chunk = blockIdx.x;
    const int b = blockIdx.y;
    const int tid = threadIdx.x;

    __shared__ float w[CROWS];
    __shared__ float part[4][DD];
    __shared__ int s_last;
    __shared__ float s_den;

    const unsigned long long bkey = g_keys[b];
    const float mx = orderkey_float((uint32_t)(bkey >> 32));
    const int n0 = chunk * CROWS;
    if (tid < CROWS)
        w[tid] = expf(g_scores[(long)b * NN + n0 + tid] - mx);
    __syncthreads();

    // partial denominator (fixed order) by thread 0
    if (tid == 0) {
        float d = 0.f;
#pragma unroll
        for (int n = 0; n < CROWS; n++) d += w[n];
        g_denp[b][chunk] = d;
    }

    const int rg = tid >> 6;        // row-group 0..3
    const int c4 = tid & 63;        // float4 column
    const float4* Vp = reinterpret_cast<const float4*>(
        V + ((long)b * NN + n0) * DD) + c4;
    float4 acc = {0.f, 0.f, 0.f, 0.f};
#pragma unroll
    for (int n = rg; n < CROWS; n += 4) {
        const float4 v = Vp[(long)n * (DD / 4)];
        const float ww = w[n];
        acc.x = fmaf(ww, v.x, acc.x);
        acc.y = fmaf(ww, v.y, acc.y);
        acc.z = fmaf(ww, v.z, acc.z);
        acc.w = fmaf(ww, v.w, acc.w);
    }
    *reinterpret_cast<float4*>(&part[rg][c4 * 4]) = acc;
    __syncthreads();
    g_part[b][chunk][tid] = part[0][tid] + part[1][tid] + part[2][tid] + part[3][tid];

    // ---- completion protocol ----
    __threadfence();                        // partials + denp visible
    if (tid == 0)
        s_last = (atomicAdd(&g_cnt[b], 1) == NCHUNK - 1);
    __syncthreads();
    if (s_last) {
        if (tid == 0) {
            float d = 0.f;
#pragma unroll 8
            for (int c = 0; c < NCHUNK; c++) d += g_denp[b][c];
            s_den = d;
            if (out_size >= BB * DD + BB)
                out[BB * DD + b] = (float)(NN - 1 - (int)(bkey & 0xFFFFFFFFu));
        }
        __syncthreads();
        float t = 0.f;
#pragma unroll 8
        for (int c = 0; c < NCHUNK; c++) t += g_part[b][c][tid];
        out[b * DD + tid] = t / s_den;
    }
}

// =====================================================================
extern "C" void kernel_launch(void* const* d_in, const int* in_sizes, int n_in,
                              void* d_out, int out_size) {
    const float* Q  = (const float*)d_in[0];
    const float* K  = (const float*)d_in[1];
    const float* V  = (const float*)d_in[2];
    const float* Wq = (const float*)d_in[3];
    const float* Wk = (const float*)d_in[4];
    const float* Wv = (const float*)d_in[5];
    float* out = (float*)d_out;

    cudaFuncSetAttribute(scores_mma_kernel,
                         cudaFuncAttributeMaxDynamicSharedMemorySize, DYN_SMEM);

    wsplit_kernel<<<HH * DD / 256, 256>>>(Wq, Wk);
    scores_mma_kernel<<<NTILES, 256, DYN_SMEM>>>(Q, K, Wv);
    weighted_kernel<<<dim3(NCHUNK, BB), 256>>>(V, out, out_size);
}